// round 12
// baseline (speedup 1.0000x reference)
#include <cuda_runtime.h>

#define M_TOTAL 8192
#define NPT 128
#define NTILES 64
#define RESULT_ELEMS (M_TOTAL * 7)   // 57344
#define THREADS 1024

// global scratch (no device allocations allowed)
__device__ unsigned int g_keys32[M_TOTAL];       // per-tile sorted key hi (score part)
__device__ unsigned int g_keyslo[M_TOTAL];       // per-tile sorted key lo (~index part)
__device__ unsigned int g_ready[NTILES];         // per-tile flag: vc+1 (0 = not yet, first run only)

// dynamic smem: 8192 uint = 32KB (sorted hi-keys of all tiles)
extern __shared__ unsigned int sk32[];

// ---------------------------------------------------------------------------
__global__ void __launch_bounds__(THREADS) fused_nms_kernel(const float* __restrict__ tr,
                                                            const int* __restrict__ tp,
                                                            float* __restrict__ out,
                                                            int writeKeep) {
    const int tile = blockIdx.x;
    const int tid = threadIdx.x;

    __shared__ float s_in[NPT * 7];              // staged raw input rows
    __shared__ unsigned long long s_keyraw[NPT];
    __shared__ float4 s_sbox[NPT];               // sorted class-shifted boxes
    __shared__ float s_area[NPT];                // sorted areas
    __shared__ unsigned int s_klo[NPT];          // sorted own-tile key lo words
    __shared__ unsigned int s_validmask[4];      // valid bits (sorted order)
    __shared__ unsigned int s_rownz[4];          // rows with any suppression bit
    __shared__ uint4 s_sup[NPT];                 // suppression bitmask rows
    __shared__ float s_rec[NPT][8];              // sorted output records
    __shared__ unsigned int s_kw[4];             // final keep bitmask
    __shared__ int s_grank[NPT];                 // global ranks (accumulated)
    __shared__ unsigned int s_vc[NTILES];        // per-tile valid counts (+1 encoding)

    // ---- phase 0: stage input + zero masks/matrices ----
    {
        const float4* src = (const float4*)(tr + (size_t)tile * NPT * 7);
        float4* dst = (float4*)s_in;
        if (tid < NPT * 7 / 4) dst[tid] = src[tid];
    }
    if (tid < 512) ((unsigned int*)s_sup)[tid] = 0;   // 128 rows x 4 words
    if (tid < 4) { s_validmask[tid] = 0; s_rownz[tid] = 0; }
    if (tid < NPT) s_grank[tid] = 0;
    __syncthreads();

    // ---- phase 1: transform, publish raw key (t < 128) ----
    const bool active = (tid < NPT);
    float b0, b1, b2, b3, score, labelf, growth, x0, x1c, x2, x3, area;
    unsigned long long mykey = 0;
    int valid = 0;
    if (active) {
        const int g = tile * NPT + tid;
        const float* r = s_in + tid * 7;
        b0 = r[0]; b1 = r[1]; b2 = r[2]; b3 = r[3];
        score = r[4]; labelf = r[5]; growth = r[6];
        const float hs = (float)tp[tile * 4 + 0];  // h_start -> cols 1,3
        const float ws = (float)tp[tile * 4 + 2];  // w_start -> cols 0,2
        b0 = fminf(fmaxf(__fadd_rn(b0, ws), 0.0f), 4096.0f);
        b1 = fminf(fmaxf(__fadd_rn(b1, hs), 0.0f), 4096.0f);
        b2 = fminf(fmaxf(__fadd_rn(b2, ws), 0.0f), 4096.0f);
        b3 = fminf(fmaxf(__fadd_rn(b3, hs), 0.0f), 4096.0f);

        valid = (score > 0.05f) ? 1 : 0;
        const float skey = valid ? score : __fsub_rn(score, 1e9f);
        unsigned int ob = __float_as_uint(skey);
        ob = (ob & 0x80000000u) ? ~ob : (ob | 0x80000000u);  // monotone float->uint
        // descending score, ties ascending global index (stable argsort)
        mykey = ((unsigned long long)ob << 32) | (unsigned int)(~(unsigned int)g);
        s_keyraw[tid] = mykey;

        const float shift = __fmul_rn(labelf, 8192.0f);      // 2*IMAGE_SIZE
        x0  = __fadd_rn(b0, shift);
        x1c = __fadd_rn(b1, shift);
        x2  = __fadd_rn(b2, shift);
        x3  = __fadd_rn(b3, shift);
        area = __fmul_rn(__fsub_rn(x2, x0), __fsub_rn(x3, x1c));
    }
    __syncthreads();

    // ---- phase 2: serial rank-sort (broadcast LDS) + scatter (t < 128) ----
    if (active) {
        int rank = 0;
        #pragma unroll 16
        for (int j = 0; j < NPT; j++) rank += (s_keyraw[j] > mykey) ? 1 : 0;

        s_sbox[rank] = make_float4(x0, x1c, x2, x3);
        s_area[rank] = area;
        s_klo[rank] = (unsigned int)mykey;
        atomicOr(&s_validmask[rank >> 5], (unsigned int)valid << (rank & 31));
        s_rec[rank][0] = b0; s_rec[rank][1] = b1; s_rec[rank][2] = b2; s_rec[rank][3] = b3;
        s_rec[rank][4] = score; s_rec[rank][5] = labelf; s_rec[rank][6] = growth;

        g_keys32[tile * NPT + rank] = (unsigned int)(mykey >> 32);
        g_keyslo[tile * NPT + rank] = (unsigned int)mykey;
    }
    __syncthreads();   // keys + validmask complete

    // ---- publish per-tile ready flag (release orders the key stores) ----
    if (tid == 0) {
        const unsigned int vc = __popc(s_validmask[0]) + __popc(s_validmask[1]) +
                                __popc(s_validmask[2]) + __popc(s_validmask[3]);
        asm volatile("st.release.gpu.u32 [%0], %1;"
                     :: "l"(g_ready + tile), "r"(vc + 1u) : "memory");
    }

    // ---- phase 3: suppression matrix; (row i, 16-col group w), warp-uniform j ----
    {
        const int i = tid & 127;
        const int w = tid >> 7;               // 0..7
        unsigned int half16 = 0;
        if (i < ((w + 1) << 4)) {             // group has some j > i
            const float4 bi = s_sbox[i];
            const float ai = s_area[i];
            #pragma unroll 4
            for (int jj = 0; jj < 16; jj++) {
                const int j = (w << 4) + jj;  // uniform across warp -> broadcast
                const float4 bj = s_sbox[j];
                const float aj = s_area[j];
                const float ltx = fmaxf(bi.x, bj.x), lty = fmaxf(bi.y, bj.y);
                const float rbx = fminf(bi.z, bj.z), rby = fminf(bi.w, bj.w);
                const float wx = fmaxf(__fsub_rn(rbx, ltx), 0.0f);
                const float wy = fmaxf(__fsub_rn(rby, lty), 0.0f);
                // inter==0 -> iou==0 exactly (union>0): never suppresses.
                if ((j > i) && (wx > 0.0f) && (wy > 0.0f)) {
                    const float inter = __fmul_rn(wx, wy);
                    const float uni = __fsub_rn(__fadd_rn(ai, aj), inter);
                    const float iou = __fdiv_rn(inter, __fadd_rn(uni, 1e-8f));
                    if (iou > 0.5f) half16 |= (1u << jj);
                }
            }
        }
        if (half16)
            atomicOr(&((unsigned int*)&s_sup[i])[w >> 1], half16 << ((w & 1) * 16));
        const unsigned int nz = __ballot_sync(0xFFFFFFFFu, half16 != 0);
        if ((tid & 31) == 0 && nz) atomicOr(&s_rownz[(tid >> 5) & 3], nz);
    }
    __syncthreads();

    // ---- phase 4 (tid 0) ∥ phase 5 (all warps): reduce + pipelined staging ----
    if (tid == 0) {
        // sparse greedy reduce over active rows
        unsigned int kw[4];
        kw[0] = s_validmask[0]; kw[1] = s_validmask[1];
        kw[2] = s_validmask[2]; kw[3] = s_validmask[3];
        #pragma unroll
        for (int w = 0; w < 4; w++) {
            const unsigned int rz = s_rownz[w];
            unsigned int act = kw[w] & rz;
            while (act) {
                const int ib = __ffs(act) - 1;
                const uint4 s = s_sup[w * 32 + ib];
                kw[0] &= ~s.x; kw[1] &= ~s.y; kw[2] &= ~s.z; kw[3] &= ~s.w;
                act = kw[w] & rz & (0xFFFFFFFEu << ib);
            }
        }
        s_kw[0] = kw[0]; s_kw[1] = kw[1]; s_kw[2] = kw[2]; s_kw[3] = kw[3];
    }

    // staging: warp wid owns tiles 2*wid and 2*wid+1; poll flag then copy keys
    {
        const int wid = tid >> 5;
        const int lane = tid & 31;
        #pragma unroll
        for (int q = 0; q < 2; q++) {
            const int t = wid * 2 + q;
            if (lane == 0) {
                unsigned int f;
                do {
                    asm volatile("ld.acquire.gpu.u32 %0, [%1];"
                                 : "=r"(f) : "l"(g_ready + t) : "memory");
                } while (f == 0u);
                s_vc[t] = f;   // vc + 1
            }
            __syncwarp();
            // 128 uints = 32 lanes x uint4
            const uint4 v = __ldcg((const uint4*)(g_keys32 + (t << 7)) + lane);
            ((uint4*)(sk32 + (t << 7)))[lane] = v;
        }
    }
    __syncthreads();

    // ---- phase 6: rank. valid -> 8-state interleaved searches; invalid -> arithmetic ----
    {
        const int e_local = tid & 127;
        const int grp = tid >> 7;                 // 0..7, 8 tiles each
        const unsigned int k32 = sk32[(tile << 7) + e_local];

        if (k32 & 0x80000000u) {
            // valid element: count strictly-greater keys (all greater keys are valid)
            const unsigned int klo = s_klo[e_local];
            const unsigned int* base = sk32 + (grp << 10);   // 8 tiles * 128
            int lo[8];
            #pragma unroll
            for (int t = 0; t < 8; t++) lo[t] = 0;
            #pragma unroll
            for (int half = 64; half >= 1; half >>= 1) {
                #pragma unroll
                for (int t = 0; t < 8; t++) {
                    if (base[(t << 7) + lo[t] + half - 1] > k32) lo[t] += half;
                }
            }
            int partial = 0;
            #pragma unroll
            for (int t = 0; t < 8; t++) {
                int j = lo[t];
                partial += j;
                // equal-hi among valid keys: essentially never; short walk via L2
                const int tb = (grp << 10) + (t << 7);
                while (j < NPT && sk32[tb + j] == k32) {
                    partial += (__ldcg(g_keyslo + tb + j) > klo) ? 1 : 0;
                    j++;
                }
            }
            if (partial) atomicAdd(&s_grank[e_local], partial);
        } else if (grp == 0) {
            // invalid element: rank = totalValid + invalidsBefore(tile) + (pos - vc_own)
            int totValid = 0, invBefore = 0;
            #pragma unroll 8
            for (int t = 0; t < NTILES; t++) {
                const int v = (int)s_vc[t] - 1;
                totValid += v;
                if (t < tile) invBefore += NPT - v;
            }
            s_grank[e_local] = totValid + invBefore + (e_local - ((int)s_vc[tile] - 1));
        }
    }
    __syncthreads();

    // ---- phase 7: fully parallel scatter (896 data threads + 128 keep threads) ----
    if (tid < 896) {
        const int e = tid / 7;
        const int c = tid - e * 7;
        const int rank = s_grank[e];
        const unsigned int kbit = (s_kw[e >> 5] >> (e & 31)) & 1u;
        const float keepf = kbit ? 1.0f : 0.0f;
        out[(size_t)rank * 7 + c] = s_rec[e][c] * keepf;
    } else if (writeKeep) {
        const int e = tid - 896;
        const int rank = s_grank[e];
        const unsigned int kbit = (s_kw[e >> 5] >> (e & 31)) & 1u;
        out[RESULT_ELEMS + rank] = kbit ? 1.0f : 0.0f;
    }
}

// tail zero-fill only for unexpected out_size layouts
__global__ void fill_zero_kernel(float* __restrict__ out, int start, int end) {
    int i = start + blockIdx.x * blockDim.x + threadIdx.x;
    if (i < end) out[i] = 0.0f;
}

// ---------------------------------------------------------------------------
extern "C" void kernel_launch(void* const* d_in, const int* in_sizes, int n_in,
                              void* d_out, int out_size) {
    const float* tr = (const float*)d_in[0];   // tile_results (64,128,7) f32
    const int*   tp = (const int*)d_in[1];     // tile_positions (64,4) i32
    float* out = (float*)d_out;

    const int writeKeep = (out_size >= RESULT_ELEMS + M_TOTAL) ? 1 : 0;
    const int covered = writeKeep ? (RESULT_ELEMS + M_TOTAL) : RESULT_ELEMS;
    if (out_size > covered) {
        const int tail = out_size - covered;
        fill_zero_kernel<<<(tail + 255) / 256, 256>>>(out, covered, out_size);
    }

    fused_nms_kernel<<<NTILES, THREADS, M_TOTAL * sizeof(unsigned int)>>>(
        tr, tp, out, writeKeep);
}

// round 13
// speedup vs baseline: 1.0226x; 1.0226x over previous
#include <cuda_runtime.h>

#define M_TOTAL 8192
#define NPT 128
#define NTILES 64
#define RESULT_ELEMS (M_TOTAL * 7)   // 57344
#define THREADS 1024

__device__ unsigned int g_keys32[M_TOTAL];
__device__ unsigned int g_keyslo[M_TOTAL];
__device__ unsigned int g_validcnt[NTILES];
__device__ unsigned long long g_bar = 0;

extern __shared__ unsigned int sk32[];   // 8192 uint = 32KB

__global__ void __launch_bounds__(THREADS) fused_nms_kernel(const float* __restrict__ tr,
                                                            const int* __restrict__ tp,
                                                            float* __restrict__ out,
                                                            int writeKeep) {
    const int tile = blockIdx.x;
    const int tid = threadIdx.x;

    __shared__ float s_in[NPT * 7];
    __shared__ unsigned long long s_keyraw[NPT];
    __shared__ float4 s_sbox[NPT];
    __shared__ float s_area[NPT];
    __shared__ unsigned int s_klo[NPT];
    __shared__ unsigned int s_validmask[4];
    __shared__ unsigned int s_wvc[4];
    __shared__ unsigned int s_rownz[4];
    __shared__ uint4 s_sup[NPT];
    __shared__ float s_rec[NPT][8];
    __shared__ unsigned int s_kw[4];
    __shared__ int s_grank[NPT];
    __shared__ unsigned int s_vc[NTILES];
    __shared__ unsigned long long s_target;

    // ========== FAST KEY PATH (threads 0-127): publish ASAP ==========
    int myrank = 0;
    unsigned long long mykey = 0;
    float score = 0.0f;
    int valid = 0;
    const bool active = (tid < NPT);

    if (active) {
        if (tid < 4) s_validmask[tid] = 0;       // before bar.sync 1 -> safe
        const int g = tile * NPT + tid;
        score = tr[(size_t)g * 7 + 4];           // scalar score load only
        valid = (score > 0.05f) ? 1 : 0;
        const float skey = valid ? score : __fsub_rn(score, 1e9f);
        unsigned int ob = __float_as_uint(skey);
        ob = (ob & 0x80000000u) ? ~ob : (ob | 0x80000000u);
        mykey = ((unsigned long long)ob << 32) | (unsigned int)(~(unsigned int)g);
        s_keyraw[tid] = mykey;
        const unsigned int bal = __ballot_sync(0xFFFFFFFFu, valid);
        if ((tid & 31) == 0) s_wvc[tid >> 5] = __popc(bal);

        asm volatile("bar.sync 1, 128;" ::: "memory");

        int rank = 0;
        #pragma unroll 16
        for (int j = 0; j < NPT; j++) rank += (s_keyraw[j] > mykey) ? 1 : 0;
        myrank = rank;

        const unsigned int khi = (unsigned int)(mykey >> 32);
        g_keys32[tile * NPT + rank] = khi;
        g_keyslo[tile * NPT + rank] = (unsigned int)mykey;
        sk32[(tile << 7) + rank] = khi;
        s_klo[rank] = (unsigned int)mykey;
        atomicOr(&s_validmask[rank >> 5], (unsigned int)valid << (rank & 31));

        asm volatile("bar.sync 1, 128;" ::: "memory");

        if (tid == 0) {
            g_validcnt[tile] = s_wvc[0] + s_wvc[1] + s_wvc[2] + s_wvc[3];
            unsigned long long ticket;
            asm volatile("atom.release.gpu.add.u64 %0, [%1], %2;"
                         : "=l"(ticket) : "l"(&g_bar), "l"(1ULL) : "memory");
            s_target = (ticket / NTILES + 1ULL) * NTILES;
        }
    } else {
        // ---- concurrent helpers (threads 128+) ----
        if (tid < 128 + 224) {
            const float4* src = (const float4*)(tr + (size_t)tile * NPT * 7);
            ((float4*)s_in)[tid - 128] = src[tid - 128];
        } else if (tid < 352 + 512) {
            ((unsigned int*)s_sup)[tid - 352] = 0;
        } else if (tid < 864 + 4) {
            s_rownz[tid - 864] = 0;
        } else if (tid < 868 + 128) {
            s_grank[tid - 868] = 0;
        }
    }
    __syncthreads();

    // ---- box transform + record scatter (t < 128), post-publish ----
    if (active) {
        const float* r = s_in + tid * 7;
        float b0 = r[0], b1 = r[1], b2 = r[2], b3 = r[3];
        const float labelf = r[5], growth = r[6];
        const float hs = (float)tp[tile * 4 + 0];
        const float ws = (float)tp[tile * 4 + 2];
        b0 = fminf(fmaxf(__fadd_rn(b0, ws), 0.0f), 4096.0f);
        b1 = fminf(fmaxf(__fadd_rn(b1, hs), 0.0f), 4096.0f);
        b2 = fminf(fmaxf(__fadd_rn(b2, ws), 0.0f), 4096.0f);
        b3 = fminf(fmaxf(__fadd_rn(b3, hs), 0.0f), 4096.0f);

        const float shift = __fmul_rn(labelf, 8192.0f);
        const float x0  = __fadd_rn(b0, shift);
        const float x1c = __fadd_rn(b1, shift);
        const float x2  = __fadd_rn(b2, shift);
        const float x3  = __fadd_rn(b3, shift);
        const float area = __fmul_rn(__fsub_rn(x2, x0), __fsub_rn(x3, x1c));

        s_sbox[myrank] = make_float4(x0, x1c, x2, x3);
        s_area[myrank] = area;
        s_rec[myrank][0] = b0; s_rec[myrank][1] = b1;
        s_rec[myrank][2] = b2; s_rec[myrank][3] = b3;
        s_rec[myrank][4] = score; s_rec[myrank][5] = labelf; s_rec[myrank][6] = growth;
    }
    __syncthreads();

    // ---- suppression matrix; (row i, 16-col group w), warp-uniform j ----
    {
        const int i = tid & 127;
        const int w = tid >> 7;
        unsigned int half16 = 0;
        if (i < ((w + 1) << 4)) {
            const float4 bi = s_sbox[i];
            const float ai = s_area[i];
            #pragma unroll 4
            for (int jj = 0; jj < 16; jj++) {
                const int j = (w << 4) + jj;
                const float4 bj = s_sbox[j];
                const float aj = s_area[j];
                const float ltx = fmaxf(bi.x, bj.x), lty = fmaxf(bi.y, bj.y);
                const float rbx = fminf(bi.z, bj.z), rby = fminf(bi.w, bj.w);
                const float wx = fmaxf(__fsub_rn(rbx, ltx), 0.0f);
                const float wy = fmaxf(__fsub_rn(rby, lty), 0.0f);
                if ((j > i) && (wx > 0.0f) && (wy > 0.0f)) {
                    const float inter = __fmul_rn(wx, wy);
                    const float uni = __fsub_rn(__fadd_rn(ai, aj), inter);
                    const float iou = __fdiv_rn(inter, __fadd_rn(uni, 1e-8f));
                    if (iou > 0.5f) half16 |= (1u << jj);
                }
            }
        }
        if (half16)
            atomicOr(&((unsigned int*)&s_sup[i])[w >> 1], half16 << ((w & 1) * 16));
        const unsigned int nz = __ballot_sync(0xFFFFFFFFu, half16 != 0);
        if ((tid & 31) == 0 && nz) atomicOr(&s_rownz[(tid >> 5) & 3], nz);
    }
    __syncthreads();

    // ---- sparse greedy reduce (single thread) + barrier poll ----
    if (tid == 0) {
        unsigned int kw[4];
        kw[0] = s_validmask[0]; kw[1] = s_validmask[1];
        kw[2] = s_validmask[2]; kw[3] = s_validmask[3];
        #pragma unroll
        for (int w = 0; w < 4; w++) {
            const unsigned int rz = s_rownz[w];
            unsigned int act = kw[w] & rz;
            while (act) {
                const int ib = __ffs(act) - 1;
                const uint4 s = s_sup[w * 32 + ib];
                kw[0] &= ~s.x; kw[1] &= ~s.y; kw[2] &= ~s.z; kw[3] &= ~s.w;
                act = kw[w] & rz & (0xFFFFFFFEu << ib);
            }
        }
        s_kw[0] = kw[0]; s_kw[1] = kw[1]; s_kw[2] = kw[2]; s_kw[3] = kw[3];

        const unsigned long long target = s_target;
        unsigned long long cur;
        do {
            asm volatile("ld.acquire.gpu.u64 %0, [%1];"
                         : "=l"(cur) : "l"(&g_bar) : "memory");
        } while (cur < target);
    }
    __syncthreads();

    // ---- stage hi-keys (skip own tile) + valid counts ----
    {
        const uint4* src = (const uint4*)g_keys32;
        uint4* dst = (uint4*)sk32;
        #pragma unroll
        for (int idx = tid; idx < M_TOTAL / 4; idx += THREADS) {
            if ((idx >> 5) != tile) dst[idx] = __ldcg(src + idx);
        }
    }
    if (tid < NTILES) s_vc[tid] = __ldcg(g_validcnt + tid);
    __syncthreads();

    // ---- rank: valid -> interleaved searches; invalid -> arithmetic ----
    {
        const int e_local = tid & 127;
        const int grp = tid >> 7;
        const unsigned int k32 = sk32[(tile << 7) + e_local];

        if (k32 & 0x80000000u) {
            const unsigned int klo = s_klo[e_local];
            const unsigned int* base = sk32 + (grp << 10);
            int lo[8];
            #pragma unroll
            for (int t = 0; t < 8; t++) lo[t] = 0;
            #pragma unroll
            for (int half = 64; half >= 1; half >>= 1) {
                #pragma unroll
                for (int t = 0; t < 8; t++) {
                    if (base[(t << 7) + lo[t] + half - 1] > k32) lo[t] += half;
                }
            }
            int partial = 0;
            #pragma unroll
            for (int t = 0; t < 8; t++) {
                int j = lo[t];
                partial += j;
                const int tb = (grp << 10) + (t << 7);
                while (j < NPT && sk32[tb + j] == k32) {
                    partial += (__ldcg(g_keyslo + tb + j) > klo) ? 1 : 0;
                    j++;
                }
            }
            if (partial) atomicAdd(&s_grank[e_local], partial);
        } else if (grp == 0) {
            int totValid = 0, invBefore = 0;
            #pragma unroll 8
            for (int t = 0; t < NTILES; t++) {
                const int v = (int)s_vc[t];
                totValid += v;
                if (t < tile) invBefore += NPT - v;
            }
            s_grank[e_local] = totValid + invBefore + (e_local - (int)s_vc[tile]);
        }
    }
    __syncthreads();

    // ---- fully parallel scatter ----
    if (tid < 896) {
        const int e = tid / 7;
        const int c = tid - e * 7;
        const int rank = s_grank[e];
        const unsigned int kbit = (s_kw[e >> 5] >> (e & 31)) & 1u;
        const float keepf = kbit ? 1.0f : 0.0f;
        out[(size_t)rank * 7 + c] = s_rec[e][c] * keepf;
    } else if (writeKeep) {
        const int e = tid - 896;
        const int rank = s_grank[e];
        const unsigned int kbit = (s_kw[e >> 5] >> (e & 31)) & 1u;
        out[RESULT_ELEMS + rank] = kbit ? 1.0f : 0.0f;
    }
}

__global__ void fill_zero_kernel(float* __restrict__ out, int start, int end) {
    int i = start + blockIdx.x * blockDim.x + threadIdx.x;
    if (i < end) out[i] = 0.0f;
}

extern "C" void kernel_launch(void* const* d_in, const int* in_sizes, int n_in,
                              void* d_out, int out_size) {
    const float* tr = (const float*)d_in[0];
    const int*   tp = (const int*)d_in[1];
    float* out = (float*)d_out;

    const int writeKeep = (out_size >= RESULT_ELEMS + M_TOTAL) ? 1 : 0;
    const int covered = writeKeep ? (RESULT_ELEMS + M_TOTAL) : RESULT_ELEMS;
    if (out_size > covered) {
        const int tail = out_size - covered;
        fill_zero_kernel<<<(tail + 255) / 256, 256>>>(out, covered, out_size);
    }

    fused_nms_kernel<<<NTILES, THREADS, M_TOTAL * sizeof(unsigned int)>>>(
        tr, tp, out, writeKeep);
}